// round 11
// baseline (speedup 1.0000x reference)
#include <cuda_runtime.h>
#include <math.h>

#define A_NUM 15
#define NUM_FG 128
#define RPN_BATCH_C 256
#define MAX_G 512
#define MAX_B 1024
#define TPB 512
#define NW (TPB / 32)

// Base anchors (BASE_SIZE=16, ratios {0.5,1,2}, scales {1,2,4,8,16})
__constant__ float c_base[60] = {
    -3.5f,   2.f,  18.5f,  13.f,   -15.f,   -4.f,  30.f,   19.f,
   -38.f,  -16.f,  53.f,   31.f,   -84.f,  -40.f,  99.f,   55.f,
  -176.f,  -88.f, 191.f,  103.f,     0.f,    0.f,  15.f,   15.f,
    -8.f,   -8.f,  23.f,   23.f,   -24.f,  -24.f,  39.f,   39.f,
   -56.f,  -56.f,  71.f,   71.f,  -120.f, -120.f, 135.f,  135.f,
     2.5f,  -3.f,  12.5f,  18.f,    -3.f,  -14.f,  18.f,   29.f,
   -14.f,  -36.f,  29.f,   51.f,   -36.f,  -80.f,  51.f,   95.f,
   -80.f, -168.f,  95.f,  183.f
};

__device__ int g_bp[MAX_B];
__device__ int g_bn[MAX_B];
__device__ unsigned long long g_pack[MAX_G];   // (iou_bits<<32)|~k ; 0 = untouched
__device__ int g_kfirst = 0x7fffffff;          // first inside anchor (global)
__device__ unsigned g_bar_count = 0;
__device__ volatile unsigned g_bar_gen = 0;

// Software grid barrier. Valid: all blocks co-resident (grid = 2 * #SMs, occ 2).
__device__ __forceinline__ void grid_barrier(int nblocks) {
    __syncthreads();
    if (threadIdx.x == 0) {
        __threadfence();
        unsigned gen = g_bar_gen;
        if (atomicAdd(&g_bar_count, 1u) == (unsigned)(nblocks - 1)) {
            atomicExch(&g_bar_count, 0u);
            __threadfence();
            g_bar_gen = gen + 1;
        } else {
            while (g_bar_gen == gen) { }
        }
        __threadfence();
    }
    __syncthreads();
}

__global__ void __launch_bounds__(TPB, 2)
k_fused(const float* __restrict__ gt, const float* __restrict__ meta,
        float* __restrict__ out, int K, int c, int G,
        int nblocks, int chunk, float inv_c) {
    __shared__ float4 s_gt[MAX_G];
    __shared__ float  s_area[MAX_G];
    __shared__ int    s_wp[NW], s_wn[NW];

    const int tid  = threadIdx.x;
    const int bid  = blockIdx.x;
    const int lane = tid & 31;
    const int warp = tid >> 5;
    const unsigned FULL = 0xffffffffu;

    for (int g = tid; g < G; g += TPB) {
        float4 b = reinterpret_cast<const float4*>(gt)[g];
        s_gt[g] = b;
        s_area[g] = (b.z - b.x + 1.0f) * (b.w - b.y + 1.0f);
    }
    __syncthreads();

    const float h = meta[0], w = meta[1];
    const float wm1 = w - 1.f, hm1 = h - 1.f;
    float*  lab = out + (size_t)8 * K;
    float4* tgt = reinterpret_cast<float4*>(out + (size_t)4 * K);

    const int base = bid * chunk;
    const int end  = min(base + chunk, K);
    const float4 gb0 = s_gt[0];

    // ============ Phase 1: per-anchor work + fused per-gt argmax ==========
    for (int sb = base; sb < end; sb += TPB) {
        int k = sb + tid;
        int kk = min(k, end - 1);
        // kk/15 and t2/c via verified float-reciprocal (no int division)
        int t2 = (int)(((float)kk + 0.5f) * (1.0f / 15.0f));
        int a  = kk - t2 * A_NUM;
        int ii = (int)(((float)t2 + 0.5f) * inv_c);
        int jj = t2 - ii * c;
        float sx = (float)(jj << 4);
        float sy = (float)(ii << 4);

        // per-warp spatial window
        float sxlo = sx, sxhi = sx, sylo = sy, syhi = sy;
        #pragma unroll
        for (int off = 16; off; off >>= 1) {
            sxlo = fminf(sxlo, __shfl_xor_sync(FULL, sxlo, off));
            sxhi = fmaxf(sxhi, __shfl_xor_sync(FULL, sxhi, off));
            sylo = fminf(sylo, __shfl_xor_sync(FULL, sylo, off));
            syhi = fmaxf(syhi, __shfl_xor_sync(FULL, syhi, off));
        }
        float xlo = sxlo - 178.f, xhi = sxhi + 193.f;
        float ylo = sylo - 170.f, yhi = syhi + 185.f;

        float x1 = sx + c_base[a * 4 + 0];
        float y1 = sy + c_base[a * 4 + 1];
        float x2 = sx + c_base[a * 4 + 2];
        float y2 = sy + c_base[a * 4 + 3];

        bool valid  = (k < end);
        bool inside = (x1 >= 0.f) && (y1 >= 0.f) && (x2 < w) && (y2 < h);
        bool need   = inside && valid;

        if (valid)
            reinterpret_cast<float4*>(out)[k] = make_float4(x1, y1, x2, y2);

        // global first-inside-anchor (one atomic per warp)
        {
            unsigned im = __ballot_sync(FULL, need);
            if (im && lane == (unsigned)(__ffs(im) - 1))
                atomicMin(&g_kfirst, k);
        }

        // inside anchors are unclipped; clip is identity here
        float cx1 = fminf(fmaxf(x1, 0.f), wm1);
        float cy1 = fminf(fmaxf(y1, 0.f), hm1);
        float cx2 = fminf(fmaxf(x2, 0.f), wm1);
        float cy2 = fminf(fmaxf(y2, 0.f), hm1);
        float areaA = (cx2 - cx1 + 1.f) * (cy2 - cy1 + 1.f);

        float bi = 0.f, bd = 1.f;     // matches "all-zero row -> argmax 0"
        int   bg = -1;

        if (__any_sync(FULL, need)) {
            for (int gbs = 0; gbs < G; gbs += 32) {
                int g = gbs + lane;
                float4 b; float ar = 0.f;
                bool ok = false;
                if (g < G) {
                    b = s_gt[g]; ar = s_area[g];
                    ok = (b.y <= yhi) && (b.w >= ylo) && (b.x <= xhi) && (b.z >= xlo);
                }
                unsigned m = __ballot_sync(FULL, ok);
                while (m) {
                    int src = __ffs(m) - 1;
                    m &= m - 1;
                    float bx = __shfl_sync(FULL, b.x, src);
                    float by = __shfl_sync(FULL, b.y, src);
                    float bz = __shfl_sync(FULL, b.z, src);
                    float bw = __shfl_sync(FULL, b.w, src);
                    float ba = __shfl_sync(FULL, ar,  src);
                    float iw = (fminf(cx2, bz) - fmaxf(cx1, bx)) + 1.f;
                    float ih = (fminf(cy2, bw) - fmaxf(cy1, by)) + 1.f;
                    float inter = fmaxf(iw, 0.f) * fmaxf(ih, 0.f);
                    float denom = (areaA + ba) - inter;
                    // per-anchor running max (cross-multiplication, exact)
                    if (inter * bd > bi * denom) {
                        bi = inter; bd = denom; bg = gbs + src;
                    }
                    // fused per-gt argmax: exact fp32 IoU, bit-monotonic pack,
                    // ~k breaks ties toward smallest k (= jnp first-occurrence)
                    if (need && inter > 0.f) {
                        float iou = __fdiv_rn(inter, denom);
                        unsigned long long pk =
                            ((unsigned long long)__float_as_uint(iou) << 32)
                            | (unsigned)(~k);
                        atomicMax(&g_pack[gbs + src], pk);   // RED, no return
                    }
                }
            }
        }

        if (!valid) continue;
        if (!inside) {
            tgt[k] = make_float4(0.f, 0.f, 0.f, 0.f);
            lab[k] = -1.f;
            continue;
        }

        float mo = __fdiv_rn(bi, bd);   // exact: feeds label thresholds
        float l = -1.f;
        if (mo < 0.3f)  l = 0.f;
        if (mo >= 0.7f) l = 1.f;
        lab[k] = l;

        float4 gb = (bg >= 0) ? s_gt[bg] : gb0;
        float ew = cx2 - cx1 + 1.f, eh = cy2 - cy1 + 1.f;
        float ecx = cx1 + 0.5f * ew, ecy = cy1 + 0.5f * eh;
        float gw = gb.z - gb.x + 1.f, gh = gb.w - gb.y + 1.f;
        float gcx = gb.x + 0.5f * gw, gcy = gb.y + 0.5f * gh;
        tgt[k] = make_float4(__fdividef(gcx - ecx, ew),
                             __fdividef(gcy - ecy, eh),
                             __logf(__fdividef(gw, ew)),
                             __logf(__fdividef(gh, eh)));
    }

    grid_barrier(nblocks);

    // ---- apply per-gt winners falling in my chunk, then count ------------
    {
        int kfirst = __ldcg(&g_kfirst);
        if (tid < G) {
            unsigned long long pk = __ldcg(&g_pack[tid]);
            int kw = (pk == 0ull) ? kfirst : (int)(~(unsigned)(pk & 0xffffffffull));
            if (kw >= base && kw < end) lab[kw] = 1.0f;
        }
    }
    __syncthreads();

    int cp = 0, cn = 0;
    for (int k = base + tid; k < end; k += TPB) {
        float l = lab[k];               // all writes here were by this block
        cp += (l == 1.f);
        cn += (l == 0.f);
    }
    #pragma unroll
    for (int off = 16; off; off >>= 1) {
        cp += __shfl_down_sync(FULL, cp, off);
        cn += __shfl_down_sync(FULL, cn, off);
    }
    if (lane == 0) { s_wp[warp] = cp; s_wn[warp] = cn; }
    __syncthreads();
    if (tid == 0) {
        int p = 0, n = 0;
        #pragma unroll
        for (int v = 0; v < NW; v++) { p += s_wp[v]; n += s_wn[v]; }
        g_bp[bid] = p; g_bn[bid] = n;
    }

    grid_barrier(nblocks);

    // ---- reset persistent state for next graph replay (post-read) --------
    if (bid == 0) {
        if (tid < G) g_pack[tid] = 0ull;
        if (tid == 0) g_kfirst = 0x7fffffff;
    }

    // ---- shfl-based scan of block counts + apply subsampling -------------
    __shared__ int s_sp[MAX_B], s_sn[MAX_B];
    int vp = (tid < nblocks) ? __ldcg(&g_bp[tid]) : 0;
    int vn = (tid < nblocks) ? __ldcg(&g_bn[tid]) : 0;
    #pragma unroll
    for (int off = 1; off < 32; off <<= 1) {
        int tp = __shfl_up_sync(FULL, vp, off);
        int tn = __shfl_up_sync(FULL, vn, off);
        if (lane >= off) { vp += tp; vn += tn; }
    }
    if (lane == 31) { s_wp[warp] = vp; s_wn[warp] = vn; }
    __syncthreads();
    if (warp == 0 && lane < NW) {
        int wv = s_wp[lane], wn2 = s_wn[lane];
        #pragma unroll
        for (int off = 1; off < NW; off <<= 1) {
            int tp = __shfl_up_sync(0xffffu, wv, off);
            int tn = __shfl_up_sync(0xffffu, wn2, off);
            if (lane >= off) { wv += tp; wn2 += tn; }
        }
        s_wp[lane] = wv; s_wn[lane] = wn2;
    }
    __syncthreads();
    if (warp > 0) { vp += s_wp[warp - 1]; vn += s_wn[warp - 1]; }
    s_sp[tid] = vp; s_sn[tid] = vn;
    __syncthreads();

    int runP = (bid > 0) ? s_sp[bid - 1] : 0;
    int runN = (bid > 0) ? s_sn[bid - 1] : 0;
    int totP = s_sp[nblocks - 1];
    const int numBg = RPN_BATCH_C - (totP < NUM_FG ? totP : NUM_FG);
    __syncthreads();

    for (int s = base; s < end; s += TPB) {
        int k = s + tid;
        float l = (k < end) ? lab[k] : -1.f;
        int pos = (l == 1.f);
        int neg = (l == 0.f);
        unsigned ballp = __ballot_sync(FULL, pos);
        unsigned balln = __ballot_sync(FULL, neg);
        if (lane == 0) { s_wp[warp] = __popc(ballp); s_wn[warp] = __popc(balln); }
        __syncthreads();
        int wp = 0, wn = 0, totPb = 0, totNb = 0;
        #pragma unroll
        for (int v = 0; v < NW; v++) {
            int a2 = s_wp[v], b2 = s_wn[v];
            if (v < warp) { wp += a2; wn += b2; }
            totPb += a2; totNb += b2;
        }
        unsigned lm = (1u << lane) - 1u;
        int rp = runP + wp + __popc(ballp & lm) + 1;
        int rn = runN + wn + __popc(balln & lm) + 1;
        if (k < end) {
            if (pos && rp > NUM_FG) lab[k] = -1.f;
            if (neg && rn > numBg)  lab[k] = -1.f;
        }
        runP += totPb; runN += totNb;
        __syncthreads();
    }
}

// ---------------------------------------------------------------------------
extern "C" void kernel_launch(void* const* d_in, const int* in_sizes, int n_in,
                              void* d_out, int out_size) {
    const float* gt   = (const float*)d_in[0];
    const float* meta = (const float*)d_in[1];
    float* out = (float*)d_out;

    int G = in_sizes[0] / 4;
    if (G > MAX_G) G = MAX_G;
    int K  = in_sizes[2];
    int rc = K / A_NUM;
    int c  = (int)(sqrt((double)rc) + 0.5);
    float inv_c = (float)(1.0 / (double)c);

    int dev = 0;
    cudaGetDevice(&dev);
    int nsm = 0;
    cudaDeviceGetAttribute(&nsm, cudaDevAttrMultiProcessorCount, dev);
    if (nsm <= 0) nsm = 148;
    int nblocks = 2 * nsm;               // 2 co-resident blocks per SM
    if (nblocks > MAX_B) nblocks = MAX_B;
    if (nblocks > TPB) nblocks = TPB;    // scan capacity
    int chunk = (K + nblocks - 1) / nblocks;

    k_fused<<<nblocks, TPB>>>(gt, meta, out, K, c, G, nblocks, chunk, inv_c);
}

// round 12
// speedup vs baseline: 3.8578x; 3.8578x over previous
#include <cuda_runtime.h>
#include <math.h>

#define A_NUM 15
#define NUM_FG 128
#define RPN_BATCH_C 256
#define MAX_G 512
#define MAX_B 1024
#define TPB 512
#define NW (TPB / 32)

// Base anchors (BASE_SIZE=16, ratios {0.5,1,2}, scales {1,2,4,8,16})
__constant__ float c_base[60] = {
    -3.5f,   2.f,  18.5f,  13.f,   -15.f,   -4.f,  30.f,   19.f,
   -38.f,  -16.f,  53.f,   31.f,   -84.f,  -40.f,  99.f,   55.f,
  -176.f,  -88.f, 191.f,  103.f,     0.f,    0.f,  15.f,   15.f,
    -8.f,   -8.f,  23.f,   23.f,   -24.f,  -24.f,  39.f,   39.f,
   -56.f,  -56.f,  71.f,   71.f,  -120.f, -120.f, 135.f,  135.f,
     2.5f,  -3.f,  12.5f,  18.f,    -3.f,  -14.f,  18.f,   29.f,
   -14.f,  -36.f,  29.f,   51.f,   -36.f,  -80.f,  51.f,   95.f,
   -80.f, -168.f,  95.f,  183.f
};

__device__ int g_bp[MAX_B];
__device__ int g_bn[MAX_B];
__device__ unsigned long long g_pack[MAX_G];   // (iou_bits<<32)|~k ; 0 = untouched
__device__ int g_kfirst = 0x7fffffff;          // first inside anchor (global)
__device__ unsigned g_bar_count = 0;
__device__ volatile unsigned g_bar_gen = 0;

// Software grid barrier. Valid: all blocks co-resident (grid = 2 * #SMs, occ 2).
__device__ __forceinline__ void grid_barrier(int nblocks) {
    __syncthreads();
    if (threadIdx.x == 0) {
        __threadfence();
        unsigned gen = g_bar_gen;
        if (atomicAdd(&g_bar_count, 1u) == (unsigned)(nblocks - 1)) {
            atomicExch(&g_bar_count, 0u);
            __threadfence();
            g_bar_gen = gen + 1;
        } else {
            while (g_bar_gen == gen) { }
        }
        __threadfence();
    }
    __syncthreads();
}

__global__ void __launch_bounds__(TPB, 2)
k_fused(const float* __restrict__ gt, const float* __restrict__ meta,
        float* __restrict__ out, int K, int c, int G,
        int nblocks, int chunk, float inv_c) {
    __shared__ float4 s_gt[MAX_G];
    __shared__ float  s_area[MAX_G];
    __shared__ int    s_wp[NW], s_wn[NW];

    const int tid  = threadIdx.x;
    const int bid  = blockIdx.x;
    const int lane = tid & 31;
    const int warp = tid >> 5;
    const unsigned FULL = 0xffffffffu;

    for (int g = tid; g < G; g += TPB) {
        float4 b = reinterpret_cast<const float4*>(gt)[g];
        s_gt[g] = b;
        s_area[g] = (b.z - b.x + 1.0f) * (b.w - b.y + 1.0f);
    }
    __syncthreads();

    const float h = meta[0], w = meta[1];
    const float wm1 = w - 1.f, hm1 = h - 1.f;
    float*  lab = out + (size_t)8 * K;
    float4* tgt = reinterpret_cast<float4*>(out + (size_t)4 * K);

    const int base = bid * chunk;
    const int end  = min(base + chunk, K);
    const float4 gb0 = s_gt[0];

    // ============ Phase 1: per-anchor work + warp-aggregated gt argmax ====
    for (int sb = base; sb < end; sb += TPB) {
        int k = sb + tid;
        int kk = min(k, end - 1);
        // kk/15 and t2/c via verified float-reciprocal (no int division)
        int t2 = (int)(((float)kk + 0.5f) * (1.0f / 15.0f));
        int a  = kk - t2 * A_NUM;
        int ii = (int)(((float)t2 + 0.5f) * inv_c);
        int jj = t2 - ii * c;
        float sx = (float)(jj << 4);
        float sy = (float)(ii << 4);

        // per-warp spatial window
        float sxlo = sx, sxhi = sx, sylo = sy, syhi = sy;
        #pragma unroll
        for (int off = 16; off; off >>= 1) {
            sxlo = fminf(sxlo, __shfl_xor_sync(FULL, sxlo, off));
            sxhi = fmaxf(sxhi, __shfl_xor_sync(FULL, sxhi, off));
            sylo = fminf(sylo, __shfl_xor_sync(FULL, sylo, off));
            syhi = fmaxf(syhi, __shfl_xor_sync(FULL, syhi, off));
        }
        float xlo = sxlo - 178.f, xhi = sxhi + 193.f;
        float ylo = sylo - 170.f, yhi = syhi + 185.f;

        float x1 = sx + c_base[a * 4 + 0];
        float y1 = sy + c_base[a * 4 + 1];
        float x2 = sx + c_base[a * 4 + 2];
        float y2 = sy + c_base[a * 4 + 3];

        bool valid  = (k < end);
        bool inside = (x1 >= 0.f) && (y1 >= 0.f) && (x2 < w) && (y2 < h);
        bool need   = inside && valid;

        if (valid)
            reinterpret_cast<float4*>(out)[k] = make_float4(x1, y1, x2, y2);

        // global first-inside-anchor (one atomic per warp)
        {
            unsigned im = __ballot_sync(FULL, need);
            if (im && lane == (unsigned)(__ffs(im) - 1))
                atomicMin(&g_kfirst, k);
        }

        // inside anchors are unclipped; clip is identity here
        float cx1 = fminf(fmaxf(x1, 0.f), wm1);
        float cy1 = fminf(fmaxf(y1, 0.f), hm1);
        float cx2 = fminf(fmaxf(x2, 0.f), wm1);
        float cy2 = fminf(fmaxf(y2, 0.f), hm1);
        float areaA = (cx2 - cx1 + 1.f) * (cy2 - cy1 + 1.f);

        float bi = 0.f, bd = 1.f;     // matches "all-zero row -> argmax 0"
        int   bg = -1;

        if (__any_sync(FULL, need)) {
            for (int gbs = 0; gbs < G; gbs += 32) {
                int g = gbs + lane;
                float4 b; float ar = 0.f;
                bool ok = false;
                if (g < G) {
                    b = s_gt[g]; ar = s_area[g];
                    ok = (b.y <= yhi) && (b.w >= ylo) && (b.x <= xhi) && (b.z >= xlo);
                }
                unsigned m = __ballot_sync(FULL, ok);
                while (m) {
                    int src = __ffs(m) - 1;
                    m &= m - 1;
                    float bx = __shfl_sync(FULL, b.x, src);
                    float by = __shfl_sync(FULL, b.y, src);
                    float bz = __shfl_sync(FULL, b.z, src);
                    float bw = __shfl_sync(FULL, b.w, src);
                    float ba = __shfl_sync(FULL, ar,  src);
                    float iw = (fminf(cx2, bz) - fmaxf(cx1, bx)) + 1.f;
                    float ih = (fminf(cy2, bw) - fmaxf(cy1, by)) + 1.f;
                    float inter = fmaxf(iw, 0.f) * fmaxf(ih, 0.f);
                    float denom = (areaA + ba) - inter;
                    // per-anchor running max (cross-multiplication, exact)
                    if (inter * bd > bi * denom) {
                        bi = inter; bd = denom; bg = gbs + src;
                    }
                    // warp-aggregated per-gt argmax for this candidate:
                    // reduce (inter, denom, k) across lanes, ONE atomic/warp.
                    float wi = need ? inter : 0.f;
                    float wd = denom;
                    int   wk = k;
                    #pragma unroll
                    for (int off = 16; off; off >>= 1) {
                        float oi = __shfl_down_sync(FULL, wi, off);
                        float od = __shfl_down_sync(FULL, wd, off);
                        int   ok2 = __shfl_down_sync(FULL, wk, off);
                        float p1 = oi * wd, p2 = wi * od;
                        bool take = (oi > 0.f) &&
                                    (wi <= 0.f || p1 > p2 ||
                                     (p1 == p2 && ok2 < wk));
                        if (take) { wi = oi; wd = od; wk = ok2; }
                    }
                    if (lane == 0 && wi > 0.f) {
                        float iou = __fdiv_rn(wi, wd);   // one division per warp
                        unsigned long long pk =
                            ((unsigned long long)__float_as_uint(iou) << 32)
                            | (unsigned)(~wk);
                        atomicMax(&g_pack[gbs + src], pk);   // RED, no return
                    }
                }
            }
        }

        if (!valid) continue;
        if (!inside) {
            tgt[k] = make_float4(0.f, 0.f, 0.f, 0.f);
            lab[k] = -1.f;
            continue;
        }

        float mo = __fdiv_rn(bi, bd);   // exact: feeds label thresholds
        float l = -1.f;
        if (mo < 0.3f)  l = 0.f;
        if (mo >= 0.7f) l = 1.f;
        lab[k] = l;

        float4 gb = (bg >= 0) ? s_gt[bg] : gb0;
        float ew = cx2 - cx1 + 1.f, eh = cy2 - cy1 + 1.f;
        float ecx = cx1 + 0.5f * ew, ecy = cy1 + 0.5f * eh;
        float gw = gb.z - gb.x + 1.f, gh = gb.w - gb.y + 1.f;
        float gcx = gb.x + 0.5f * gw, gcy = gb.y + 0.5f * gh;
        tgt[k] = make_float4(__fdividef(gcx - ecx, ew),
                             __fdividef(gcy - ecy, eh),
                             __logf(__fdividef(gw, ew)),
                             __logf(__fdividef(gh, eh)));
    }

    grid_barrier(nblocks);

    // ---- apply per-gt winners falling in my chunk, then count ------------
    {
        int kfirst = __ldcg(&g_kfirst);
        if (tid < G) {
            unsigned long long pk = __ldcg(&g_pack[tid]);
            int kw = (pk == 0ull) ? kfirst : (int)(~(unsigned)(pk & 0xffffffffull));
            if (kw >= base && kw < end) lab[kw] = 1.0f;
        }
    }
    __syncthreads();

    int cp = 0, cn = 0;
    for (int k = base + tid; k < end; k += TPB) {
        float l = lab[k];               // all writes here were by this block
        cp += (l == 1.f);
        cn += (l == 0.f);
    }
    #pragma unroll
    for (int off = 16; off; off >>= 1) {
        cp += __shfl_down_sync(FULL, cp, off);
        cn += __shfl_down_sync(FULL, cn, off);
    }
    if (lane == 0) { s_wp[warp] = cp; s_wn[warp] = cn; }
    __syncthreads();
    if (tid == 0) {
        int p = 0, n = 0;
        #pragma unroll
        for (int v = 0; v < NW; v++) { p += s_wp[v]; n += s_wn[v]; }
        g_bp[bid] = p; g_bn[bid] = n;
    }

    grid_barrier(nblocks);

    // ---- reset persistent state for next graph replay (post-read) --------
    if (bid == 0) {
        if (tid < G) g_pack[tid] = 0ull;
        if (tid == 0) g_kfirst = 0x7fffffff;
    }

    // ---- shfl-based scan of block counts + apply subsampling -------------
    __shared__ int s_sp[MAX_B], s_sn[MAX_B];
    int vp = (tid < nblocks) ? __ldcg(&g_bp[tid]) : 0;
    int vn = (tid < nblocks) ? __ldcg(&g_bn[tid]) : 0;
    #pragma unroll
    for (int off = 1; off < 32; off <<= 1) {
        int tp = __shfl_up_sync(FULL, vp, off);
        int tn = __shfl_up_sync(FULL, vn, off);
        if (lane >= off) { vp += tp; vn += tn; }
    }
    if (lane == 31) { s_wp[warp] = vp; s_wn[warp] = vn; }
    __syncthreads();
    if (warp == 0 && lane < NW) {
        int wv = s_wp[lane], wn2 = s_wn[lane];
        #pragma unroll
        for (int off = 1; off < NW; off <<= 1) {
            int tp = __shfl_up_sync(0xffffu, wv, off);
            int tn = __shfl_up_sync(0xffffu, wn2, off);
            if (lane >= off) { wv += tp; wn2 += tn; }
        }
        s_wp[lane] = wv; s_wn[lane] = wn2;
    }
    __syncthreads();
    if (warp > 0) { vp += s_wp[warp - 1]; vn += s_wn[warp - 1]; }
    s_sp[tid] = vp; s_sn[tid] = vn;
    __syncthreads();

    int runP = (bid > 0) ? s_sp[bid - 1] : 0;
    int runN = (bid > 0) ? s_sn[bid - 1] : 0;
    int totP = s_sp[nblocks - 1];
    const int numBg = RPN_BATCH_C - (totP < NUM_FG ? totP : NUM_FG);
    __syncthreads();

    for (int s = base; s < end; s += TPB) {
        int k = s + tid;
        float l = (k < end) ? lab[k] : -1.f;
        int pos = (l == 1.f);
        int neg = (l == 0.f);
        unsigned ballp = __ballot_sync(FULL, pos);
        unsigned balln = __ballot_sync(FULL, neg);
        if (lane == 0) { s_wp[warp] = __popc(ballp); s_wn[warp] = __popc(balln); }
        __syncthreads();
        int wp = 0, wn = 0, totPb = 0, totNb = 0;
        #pragma unroll
        for (int v = 0; v < NW; v++) {
            int a2 = s_wp[v], b2 = s_wn[v];
            if (v < warp) { wp += a2; wn += b2; }
            totPb += a2; totNb += b2;
        }
        unsigned lm = (1u << lane) - 1u;
        int rp = runP + wp + __popc(ballp & lm) + 1;
        int rn = runN + wn + __popc(balln & lm) + 1;
        if (k < end) {
            if (pos && rp > NUM_FG) lab[k] = -1.f;
            if (neg && rn > numBg)  lab[k] = -1.f;
        }
        runP += totPb; runN += totNb;
        __syncthreads();
    }
}

// ---------------------------------------------------------------------------
extern "C" void kernel_launch(void* const* d_in, const int* in_sizes, int n_in,
                              void* d_out, int out_size) {
    const float* gt   = (const float*)d_in[0];
    const float* meta = (const float*)d_in[1];
    float* out = (float*)d_out;

    int G = in_sizes[0] / 4;
    if (G > MAX_G) G = MAX_G;
    int K  = in_sizes[2];
    int rc = K / A_NUM;
    int c  = (int)(sqrt((double)rc) + 0.5);
    float inv_c = (float)(1.0 / (double)c);

    int dev = 0;
    cudaGetDevice(&dev);
    int nsm = 0;
    cudaDeviceGetAttribute(&nsm, cudaDevAttrMultiProcessorCount, dev);
    if (nsm <= 0) nsm = 148;
    int nblocks = 2 * nsm;               // 2 co-resident blocks per SM
    if (nblocks > MAX_B) nblocks = MAX_B;
    if (nblocks > TPB) nblocks = TPB;    // scan capacity
    int chunk = (K + nblocks - 1) / nblocks;

    k_fused<<<nblocks, TPB>>>(gt, meta, out, K, c, G, nblocks, chunk, inv_c);
}